// round 7
// baseline (speedup 1.0000x reference)
#include <cuda_runtime.h>
#include <cuda_fp16.h>
#include <cstdint>
#include <cstddef>

// ============================================================================
// Problem constants
// ============================================================================
#define M_TOTAL 8192
#define N_TOTAL 4096
#define K_TOTAL 4096

#define TILE_M 128
#define TILE_N 256
#define TILE_K 64            // fp16 elems per stage row-chunk (128 bytes)
#define STAGES 4
#define NITER (K_TOTAL / TILE_K)   // 64

#define A_STAGE_BYTES (TILE_M * 128)          // 16384
#define B_STAGE_BYTES (TILE_N * 128)          // 32768
#define STAGE_BYTES (A_STAGE_BYTES + B_STAGE_BYTES)   // 49152
#define SMEM_TOTAL (STAGES * STAGE_BYTES)             // 196608

// ============================================================================
// Device scratch (allocation-free: __device__ globals)
// ============================================================================
__device__ __half g_xh[(size_t)M_TOTAL * K_TOTAL];   // 64 MB  x in fp16, [M,K]
__device__ __half g_wh[(size_t)N_TOTAL * K_TOTAL];   // 32 MB  unpacked q in fp16, [N,K]
__device__ float  g_bias[N_TOTAL];

// ============================================================================
// PTX helpers (baseline sm_103 target — NO 'a'-suffix features)
// ============================================================================
__device__ __forceinline__ uint32_t smem_u32(const void* p) {
    uint32_t a;
    asm("{ .reg .u64 t; cvta.to.shared.u64 t, %1; cvt.u32.u64 %0, t; }" : "=r"(a) : "l"(p));
    return a;
}

#define CP_ASYNC16(smem, gmem) \
    asm volatile("cp.async.cg.shared.global [%0], [%1], 16;" \
                 :: "r"(smem), "l"(gmem) : "memory")
#define CP_COMMIT() asm volatile("cp.async.commit_group;" ::: "memory")
#define CP_WAIT()   asm volatile("cp.async.wait_group %0;" :: "n"(STAGES - 2) : "memory")

#define LDMATRIX_X4(r0, r1, r2, r3, addr) \
    asm volatile("ldmatrix.sync.aligned.m8n8.x4.shared.b16 {%0,%1,%2,%3}, [%4];" \
                 : "=r"(r0), "=r"(r1), "=r"(r2), "=r"(r3) : "r"(addr))

__device__ __forceinline__ void mma16816(float* c, const uint32_t* a, const uint32_t* b) {
    asm volatile(
        "mma.sync.aligned.m16n8k16.row.col.f32.f16.f16.f32 "
        "{%0,%1,%2,%3}, {%4,%5,%6,%7}, {%8,%9}, {%0,%1,%2,%3};"
        : "+f"(c[0]), "+f"(c[1]), "+f"(c[2]), "+f"(c[3])
        : "r"(a[0]), "r"(a[1]), "r"(a[2]), "r"(a[3]), "r"(b[0]), "r"(b[1]));
}

// ============================================================================
// Pre-pass kernels
// ============================================================================
__global__ void convert_x_kernel(const float* __restrict__ x) {
    int i = blockIdx.x * blockDim.x + threadIdx.x;   // one float4 per thread
    float4 v = reinterpret_cast<const float4*>(x)[i];
    __half2* o = reinterpret_cast<__half2*>(g_xh) + (size_t)i * 2;
    o[0] = __floats2half2_rn(v.x, v.y);
    o[1] = __floats2half2_rn(v.z, v.w);
}

__global__ void unpack_w_kernel(const int* __restrict__ pw,
                                const int* __restrict__ pb,
                                const float* __restrict__ scale_b) {
    int i = blockIdx.x * blockDim.x + threadIdx.x;   // one packed byte per thread
    int b = pw[i];
    int hi = ((b >> 4) & 15) - 8;
    int lo = (b & 15) - 8;
    reinterpret_cast<__half2*>(g_wh)[i] =
        __halves2half2(__int2half_rn(hi), __int2half_rn(lo));
    if (i < N_TOTAL / 2) {   // fused bias dequant
        float sb = *scale_b;
        int bb = pb[i];
        g_bias[2 * i]     = sb * (float)(((bb >> 4) & 15) - 8);
        g_bias[2 * i + 1] = sb * (float)((bb & 15) - 8);
    }
}

// ============================================================================
// GEMM: 256 threads, CTA tile 128x256, warp tile 64x64 (2 M-warps x 4 N-warps)
// 4-stage cp.async pipeline, swizzled SMEM, ldmatrix + mma.sync m16n8k16.
// Round-5/6: bigger warp tile cuts SMEM-crossbar traffic per MAC
// (the round-4 co-limiter); frag double-buffering hides LDS latency in-warp.
// ============================================================================
__global__ void __launch_bounds__(256, 1) gemm_kernel(
    float* __restrict__ out, const float* __restrict__ scale_w_p)
{
    extern __shared__ __align__(1024) char smem[];
    const uint32_t sb = smem_u32(smem);

    const int tid = threadIdx.x;
    const int wid = tid >> 5;
    const int lid = tid & 31;
    const int warp_m = wid & 1;   // 0..1
    const int warp_n = wid >> 1;  // 0..3

    const int m0 = blockIdx.y * TILE_M;
    const int n0 = blockIdx.x * TILE_N;

    // ---- cp.async per-thread constants ----
    const int ld_row = tid >> 3;          // 0..31 row-subgroup
    const int ld_chk = tid & 7;           // 0..7  16B column chunk
    const __half* gA = g_xh + (size_t)(m0 + ld_row) * K_TOTAL + ld_chk * 8;
    const __half* gB = g_wh + (size_t)(n0 + ld_row) * K_TOTAL + ld_chk * 8;
    const uint32_t sw_off = (uint32_t)((ld_chk ^ (ld_row & 7)) << 4);

    // ---- ldmatrix per-lane constants ----
    const int s7 = lid & 7;               // swizzle xor term (row & 7 invariant)
    const int q  = lid >> 3;              // 0..3
    const int a_row = warp_m * 64 + ((q & 1) << 3) + s7;
    const int kc_a = q >> 1;              // 0/1: 16B chunk within k16
    const int b_row = warp_n * 64 + ((q >> 1) << 3) + s7;
    const int kc_b = q & 1;

    float acc[4][8][4];
    #pragma unroll
    for (int mt = 0; mt < 4; mt++)
        #pragma unroll
        for (int nt = 0; nt < 8; nt++)
            #pragma unroll
            for (int e = 0; e < 4; e++) acc[mt][nt][e] = 0.0f;

    // ---- prologue: prefetch stages 0..STAGES-2 ----
    #pragma unroll
    for (int p = 0; p < STAGES - 1; p++) {
        const uint32_t sA = sb + p * STAGE_BYTES;
        const uint32_t sB = sA + A_STAGE_BYTES;
        const int k0 = p * TILE_K;
        #pragma unroll
        for (int i = 0; i < 4; i++)
            CP_ASYNC16(sA + (i * 32 + ld_row) * 128 + sw_off,
                       gA + (size_t)i * 32 * K_TOTAL + k0);
        #pragma unroll
        for (int i = 0; i < 8; i++)
            CP_ASYNC16(sB + (i * 32 + ld_row) * 128 + sw_off,
                       gB + (size_t)i * 32 * K_TOTAL + k0);
        CP_COMMIT();
    }

    // ---- mainloop (single barrier per iteration, frag double-buffer) ----
    int buf = 0;
    int nbuf = STAGES - 1;
    for (int kt = 0; kt < NITER; kt++) {
        CP_WAIT();         // stage kt arrived (this thread)
        __syncthreads();   // publish; nobody still reads nbuf

        if (kt + STAGES - 1 < NITER) {
            const uint32_t sA = sb + nbuf * STAGE_BYTES;
            const uint32_t sB = sA + A_STAGE_BYTES;
            const int k0 = (kt + STAGES - 1) * TILE_K;
            #pragma unroll
            for (int i = 0; i < 4; i++)
                CP_ASYNC16(sA + (i * 32 + ld_row) * 128 + sw_off,
                           gA + (size_t)i * 32 * K_TOTAL + k0);
            #pragma unroll
            for (int i = 0; i < 8; i++)
                CP_ASYNC16(sB + (i * 32 + ld_row) * 128 + sw_off,
                           gB + (size_t)i * 32 * K_TOTAL + k0);
        }
        CP_COMMIT();       // uniform group count (empty group in tail)

        const uint32_t sA = sb + buf * STAGE_BYTES;
        const uint32_t sB = sA + A_STAGE_BYTES;
        const uint32_t aBase = sA + a_row * 128;
        const uint32_t bBase = sB + b_row * 128;

        uint32_t a_frag[2][4][4];
        uint32_t b_frag[2][8][2];

        // preload ks=0 into slot 0
        {
            const uint32_t aoff = (uint32_t)((kc_a ^ s7) << 4);
            const uint32_t boff = (uint32_t)((kc_b ^ s7) << 4);
            #pragma unroll
            for (int j = 0; j < 4; j++)
                LDMATRIX_X4(b_frag[0][2 * j][0], b_frag[0][2 * j][1],
                            b_frag[0][2 * j + 1][0], b_frag[0][2 * j + 1][1],
                            bBase + j * 2048 + boff);
            #pragma unroll
            for (int mt = 0; mt < 4; mt++)
                LDMATRIX_X4(a_frag[0][mt][0], a_frag[0][mt][1],
                            a_frag[0][mt][2], a_frag[0][mt][3],
                            aBase + mt * 2048 + aoff);
        }

        #pragma unroll
        for (int ks = 0; ks < 4; ks++) {
            const int cur = ks & 1;
            const int nxt = cur ^ 1;
            if (ks < 3) {   // prefetch ks+1 frags before consuming ks
                const uint32_t aoff = (uint32_t)((((ks + 1) * 2 + kc_a) ^ s7) << 4);
                const uint32_t boff = (uint32_t)((((ks + 1) * 2 + kc_b) ^ s7) << 4);
                #pragma unroll
                for (int j = 0; j < 4; j++)
                    LDMATRIX_X4(b_frag[nxt][2 * j][0], b_frag[nxt][2 * j][1],
                                b_frag[nxt][2 * j + 1][0], b_frag[nxt][2 * j + 1][1],
                                bBase + j * 2048 + boff);
                #pragma unroll
                for (int mt = 0; mt < 4; mt++)
                    LDMATRIX_X4(a_frag[nxt][mt][0], a_frag[nxt][mt][1],
                                a_frag[nxt][mt][2], a_frag[nxt][mt][3],
                                aBase + mt * 2048 + aoff);
            }
            #pragma unroll
            for (int mt = 0; mt < 4; mt++)
                #pragma unroll
                for (int nt = 0; nt < 8; nt++)
                    mma16816(acc[mt][nt], a_frag[cur][mt], b_frag[cur][nt]);
        }

        buf = (buf + 1 == STAGES) ? 0 : buf + 1;
        nbuf = (nbuf + 1 == STAGES) ? 0 : nbuf + 1;
    }

    // ---- epilogue ----
    const float sw = __ldg(scale_w_p);
    const int mrow = m0 + warp_m * 64 + (lid >> 2);
    const int ncol = n0 + warp_n * 64 + (lid & 3) * 2;

    #pragma unroll
    for (int mt = 0; mt < 4; mt++) {
        #pragma unroll
        for (int nt = 0; nt < 8; nt++) {
            const int m1 = mrow + mt * 16;
            const int n1 = ncol + nt * 8;
            const float b0 = g_bias[n1];
            const float b1 = g_bias[n1 + 1];
            float2 v0 = make_float2(fmaf(sw, acc[mt][nt][0], b0),
                                    fmaf(sw, acc[mt][nt][1], b1));
            float2 v1 = make_float2(fmaf(sw, acc[mt][nt][2], b0),
                                    fmaf(sw, acc[mt][nt][3], b1));
            __stcs(reinterpret_cast<float2*>(out + (size_t)m1 * N_TOTAL + n1), v0);
            __stcs(reinterpret_cast<float2*>(out + (size_t)(m1 + 8) * N_TOTAL + n1), v1);
        }
    }
}

// ============================================================================
// Host
// ============================================================================
extern "C" void kernel_launch(void* const* d_in, const int* in_sizes, int n_in,
                              void* d_out, int out_size) {
    const float* x   = (const float*)d_in[0];
    const int* pw    = (const int*)d_in[1];
    const int* pb    = (const int*)d_in[2];
    const float* sw  = (const float*)d_in[3];
    const float* sbp = (const float*)d_in[4];
    float* out = (float*)d_out;

    convert_x_kernel<<<(M_TOTAL * K_TOTAL / 4) / 256, 256>>>(x);
    unpack_w_kernel<<<(N_TOTAL * K_TOTAL / 2) / 256, 256>>>(pw, pb, sbp);

    cudaFuncSetAttribute(gemm_kernel, cudaFuncAttributeMaxDynamicSharedMemorySize, SMEM_TOTAL);
    dim3 grid(N_TOTAL / TILE_N, M_TOTAL / TILE_M);   // (16, 64)
    gemm_kernel<<<grid, 256, SMEM_TOTAL>>>(out, sw);
}

// round 8
// speedup vs baseline: 1.1502x; 1.1502x over previous
#include <cuda_runtime.h>
#include <cuda_fp16.h>
#include <cstdint>
#include <cstddef>

// ============================================================================
// Problem constants
// ============================================================================
#define M_TOTAL 8192
#define N_TOTAL 4096
#define K_TOTAL 4096

#define TILE_M 128
#define TILE_N 128
#define TILE_K 64            // fp16 elems per stage row-chunk (128 bytes)
#define STAGES 3             // 96KB -> two CTAs per SM
#define NITER (K_TOTAL / TILE_K)   // 64

#define A_STAGE_BYTES (TILE_M * 128)          // 16384
#define B_STAGE_BYTES (TILE_N * 128)          // 16384
#define STAGE_BYTES (A_STAGE_BYTES + B_STAGE_BYTES)   // 32768
#define SMEM_TOTAL (STAGES * STAGE_BYTES)             // 98304

// ============================================================================
// Device scratch (allocation-free: __device__ globals)
// ============================================================================
__device__ __half g_xh[(size_t)M_TOTAL * K_TOTAL];   // 64 MB  x in fp16, [M,K]
__device__ __half g_wh[(size_t)N_TOTAL * K_TOTAL];   // 32 MB  unpacked q in fp16, [N,K]
__device__ float  g_bias[N_TOTAL];

// ============================================================================
// PTX helpers (baseline sm_103 target — NO 'a'-suffix features)
// ============================================================================
__device__ __forceinline__ uint32_t smem_u32(const void* p) {
    uint32_t a;
    asm("{ .reg .u64 t; cvta.to.shared.u64 t, %1; cvt.u32.u64 %0, t; }" : "=r"(a) : "l"(p));
    return a;
}

#define CP_ASYNC16(smem, gmem) \
    asm volatile("cp.async.cg.shared.global [%0], [%1], 16;" \
                 :: "r"(smem), "l"(gmem) : "memory")
#define CP_COMMIT() asm volatile("cp.async.commit_group;" ::: "memory")
#define CP_WAIT()   asm volatile("cp.async.wait_group %0;" :: "n"(STAGES - 2) : "memory")

#define LDMATRIX_X4(r0, r1, r2, r3, addr) \
    asm volatile("ldmatrix.sync.aligned.m8n8.x4.shared.b16 {%0,%1,%2,%3}, [%4];" \
                 : "=r"(r0), "=r"(r1), "=r"(r2), "=r"(r3) : "r"(addr))

__device__ __forceinline__ void mma16816(float* c, const uint32_t* a, const uint32_t* b) {
    asm volatile(
        "mma.sync.aligned.m16n8k16.row.col.f32.f16.f16.f32 "
        "{%0,%1,%2,%3}, {%4,%5,%6,%7}, {%8,%9}, {%0,%1,%2,%3};"
        : "+f"(c[0]), "+f"(c[1]), "+f"(c[2]), "+f"(c[3])
        : "r"(a[0]), "r"(a[1]), "r"(a[2]), "r"(a[3]), "r"(b[0]), "r"(b[1]));
}

// ============================================================================
// Fused pre-pass: x fp32->fp16, W int4->fp16, bias dequant. Same trip count
// for x (8.39M float4) and W (8.39M packed bytes) -> one launch.
// ============================================================================
__global__ void prepass_kernel(const float* __restrict__ x,
                               const int* __restrict__ pw,
                               const int* __restrict__ pb,
                               const float* __restrict__ scale_b) {
    int i = blockIdx.x * blockDim.x + threadIdx.x;
    // x: one float4 -> 2 half2
    float4 v = reinterpret_cast<const float4*>(x)[i];
    __half2* o = reinterpret_cast<__half2*>(g_xh) + (size_t)i * 2;
    o[0] = __floats2half2_rn(v.x, v.y);
    o[1] = __floats2half2_rn(v.z, v.w);
    // W: one packed byte -> half2
    int b = pw[i];
    int hi = ((b >> 4) & 15) - 8;
    int lo = (b & 15) - 8;
    reinterpret_cast<__half2*>(g_wh)[i] =
        __halves2half2(__int2half_rn(hi), __int2half_rn(lo));
    // bias
    if (i < N_TOTAL / 2) {
        float sb = *scale_b;
        int bb = pb[i];
        g_bias[2 * i]     = sb * (float)(((bb >> 4) & 15) - 8);
        g_bias[2 * i + 1] = sb * (float)((bb & 15) - 8);
    }
}

// ============================================================================
// GEMM: 256 threads, CTA tile 128x128, warp tile 64x32 (2 M-warps x 4 N-warps)
// 3-stage cp.async pipeline, swizzled SMEM, ldmatrix + mma.sync m16n8k16,
// 2 CTAs/SM, single barrier per k-iter (round-4 base).
// Round-8 change: B-frag double-buffering (+8 regs, stays under the 128-reg
// 2-CTA budget) — B(ks+1) LDSMs issue before MMAs(ks) so only the A-load
// chain is exposed at each ks boundary.
// ============================================================================
__global__ void __launch_bounds__(256, 2) gemm_kernel(
    float* __restrict__ out, const float* __restrict__ scale_w_p)
{
    extern __shared__ __align__(1024) char smem[];
    const uint32_t sb = smem_u32(smem);

    const int tid = threadIdx.x;
    const int wid = tid >> 5;
    const int lid = tid & 31;
    const int warp_m = wid & 1;   // 0..1
    const int warp_n = wid >> 1;  // 0..3

    const int m0 = blockIdx.y * TILE_M;
    const int n0 = blockIdx.x * TILE_N;

    // ---- cp.async per-thread constants ----
    const int ld_row = tid >> 3;          // 0..31 row-subgroup
    const int ld_chk = tid & 7;           // 0..7  16B column chunk
    const __half* gA = g_xh + (size_t)(m0 + ld_row) * K_TOTAL + ld_chk * 8;
    const __half* gB = g_wh + (size_t)(n0 + ld_row) * K_TOTAL + ld_chk * 8;
    const uint32_t sw_off = (uint32_t)((ld_chk ^ (ld_row & 7)) << 4);

    // ---- ldmatrix per-lane constants ----
    const int s7 = lid & 7;               // swizzle xor term (row & 7 invariant)
    const int q  = lid >> 3;              // 0..3
    const int a_row = warp_m * 64 + ((q & 1) << 3) + s7;
    const int kc_a = q >> 1;
    const int b_row = warp_n * 32 + ((q >> 1) << 3) + s7;
    const int kc_b = q & 1;

    float acc[4][4][4];
    #pragma unroll
    for (int mt = 0; mt < 4; mt++)
        #pragma unroll
        for (int nt = 0; nt < 4; nt++)
            #pragma unroll
            for (int e = 0; e < 4; e++) acc[mt][nt][e] = 0.0f;

    // ---- prologue: prefetch stages 0..1 ----
    #pragma unroll
    for (int p = 0; p < STAGES - 1; p++) {
        const uint32_t sA = sb + p * STAGE_BYTES;
        const uint32_t sB = sA + A_STAGE_BYTES;
        const int k0 = p * TILE_K;
        #pragma unroll
        for (int i = 0; i < 4; i++)
            CP_ASYNC16(sA + (i * 32 + ld_row) * 128 + sw_off,
                       gA + (size_t)i * 32 * K_TOTAL + k0);
        #pragma unroll
        for (int i = 0; i < 4; i++)
            CP_ASYNC16(sB + (i * 32 + ld_row) * 128 + sw_off,
                       gB + (size_t)i * 32 * K_TOTAL + k0);
        CP_COMMIT();
    }

    // ---- mainloop (single barrier per iteration, B-frag double-buffer) ----
    int buf = 0;
    int nbuf = STAGES - 1;
    for (int kt = 0; kt < NITER; kt++) {
        CP_WAIT();         // stage kt arrived (this thread)
        __syncthreads();   // publish; nobody still reads nbuf

        if (kt + STAGES - 1 < NITER) {
            const uint32_t sA = sb + nbuf * STAGE_BYTES;
            const uint32_t sB = sA + A_STAGE_BYTES;
            const int k0 = (kt + STAGES - 1) * TILE_K;
            #pragma unroll
            for (int i = 0; i < 4; i++)
                CP_ASYNC16(sA + (i * 32 + ld_row) * 128 + sw_off,
                           gA + (size_t)i * 32 * K_TOTAL + k0);
            #pragma unroll
            for (int i = 0; i < 4; i++)
                CP_ASYNC16(sB + (i * 32 + ld_row) * 128 + sw_off,
                           gB + (size_t)i * 32 * K_TOTAL + k0);
        }
        CP_COMMIT();       // uniform group count (empty group in tail)

        const uint32_t sA = sb + buf * STAGE_BYTES;
        const uint32_t sB = sA + A_STAGE_BYTES;
        const uint32_t aBase = sA + a_row * 128;
        const uint32_t bBase = sB + b_row * 128;

        uint32_t b_frag[2][4][2];
        // preload B for ks=0
        {
            const uint32_t boff = (uint32_t)((kc_b ^ s7) << 4);
            #pragma unroll
            for (int j = 0; j < 2; j++)
                LDMATRIX_X4(b_frag[0][2 * j][0], b_frag[0][2 * j][1],
                            b_frag[0][2 * j + 1][0], b_frag[0][2 * j + 1][1],
                            bBase + j * 2048 + boff);
        }

        #pragma unroll
        for (int ks = 0; ks < 4; ks++) {
            const int cur = ks & 1;
            const int nxt = cur ^ 1;
            uint32_t a_frag[4][4];
            const uint32_t aoff = (uint32_t)(((ks * 2 + kc_a) ^ s7) << 4);
            #pragma unroll
            for (int mt = 0; mt < 4; mt++)
                LDMATRIX_X4(a_frag[mt][0], a_frag[mt][1], a_frag[mt][2], a_frag[mt][3],
                            aBase + mt * 2048 + aoff);
            if (ks < 3) {   // prefetch B(ks+1) before consuming ks
                const uint32_t boff = (uint32_t)((((ks + 1) * 2 + kc_b) ^ s7) << 4);
                #pragma unroll
                for (int j = 0; j < 2; j++)
                    LDMATRIX_X4(b_frag[nxt][2 * j][0], b_frag[nxt][2 * j][1],
                                b_frag[nxt][2 * j + 1][0], b_frag[nxt][2 * j + 1][1],
                                bBase + j * 2048 + boff);
            }
            #pragma unroll
            for (int mt = 0; mt < 4; mt++)
                #pragma unroll
                for (int nt = 0; nt < 4; nt++)
                    mma16816(acc[mt][nt], a_frag[mt], b_frag[cur][nt]);
        }

        buf = (buf + 1 == STAGES) ? 0 : buf + 1;
        nbuf = (nbuf + 1 == STAGES) ? 0 : nbuf + 1;
    }

    // ---- epilogue ----
    const float sw = __ldg(scale_w_p);
    const int mrow = m0 + warp_m * 64 + (lid >> 2);
    const int ncol = n0 + warp_n * 32 + (lid & 3) * 2;

    #pragma unroll
    for (int mt = 0; mt < 4; mt++) {
        #pragma unroll
        for (int nt = 0; nt < 4; nt++) {
            const int m1 = mrow + mt * 16;
            const int n1 = ncol + nt * 8;
            const float b0 = g_bias[n1];
            const float b1 = g_bias[n1 + 1];
            float2 v0 = make_float2(fmaf(sw, acc[mt][nt][0], b0),
                                    fmaf(sw, acc[mt][nt][1], b1));
            float2 v1 = make_float2(fmaf(sw, acc[mt][nt][2], b0),
                                    fmaf(sw, acc[mt][nt][3], b1));
            __stcs(reinterpret_cast<float2*>(out + (size_t)m1 * N_TOTAL + n1), v0);
            __stcs(reinterpret_cast<float2*>(out + (size_t)(m1 + 8) * N_TOTAL + n1), v1);
        }
    }
}

// ============================================================================
// Host
// ============================================================================
extern "C" void kernel_launch(void* const* d_in, const int* in_sizes, int n_in,
                              void* d_out, int out_size) {
    const float* x   = (const float*)d_in[0];
    const int* pw    = (const int*)d_in[1];
    const int* pb    = (const int*)d_in[2];
    const float* sw  = (const float*)d_in[3];
    const float* sbp = (const float*)d_in[4];
    float* out = (float*)d_out;

    // x float4 count == packed-w byte count == 8.39M -> single fused launch
    prepass_kernel<<<(M_TOTAL * K_TOTAL / 4) / 256, 256>>>(x, pw, pb, sbp);

    cudaFuncSetAttribute(gemm_kernel, cudaFuncAttributeMaxDynamicSharedMemorySize, SMEM_TOTAL);
    dim3 grid(N_TOTAL / TILE_N, M_TOTAL / TILE_M);   // (32, 64)
    gemm_kernel<<<grid, 256, SMEM_TOTAL>>>(out, sw);
}

// round 9
// speedup vs baseline: 1.1724x; 1.0193x over previous
#include <cuda_runtime.h>
#include <cuda_fp16.h>
#include <cstdint>
#include <cstddef>

// ============================================================================
// Problem constants
// ============================================================================
#define M_TOTAL 8192
#define N_TOTAL 4096
#define K_TOTAL 4096

#define TILE_M 128
#define TILE_N 128
#define TILE_K 64            // fp16 elems per stage row-chunk (128 bytes)
#define STAGES 3             // 96KB -> two CTAs per SM
#define NITER (K_TOTAL / TILE_K)   // 64

#define A_STAGE_BYTES (TILE_M * 128)          // 16384
#define B_STAGE_BYTES (TILE_N * 128)          // 16384
#define STAGE_BYTES (A_STAGE_BYTES + B_STAGE_BYTES)   // 32768
#define SMEM_TOTAL (STAGES * STAGE_BYTES)             // 98304

// ============================================================================
// Device scratch (allocation-free: __device__ globals)
// ============================================================================
__device__ __half g_xh[(size_t)M_TOTAL * K_TOTAL];   // 64 MB  x in fp16, [M,K]
__device__ __half g_wh[(size_t)N_TOTAL * K_TOTAL];   // 32 MB  unpacked q in fp16, [N,K]
__device__ float  g_bias[N_TOTAL];

// ============================================================================
// PTX helpers (baseline sm_103 target — NO 'a'-suffix features)
// ============================================================================
__device__ __forceinline__ uint32_t smem_u32(const void* p) {
    uint32_t a;
    asm("{ .reg .u64 t; cvta.to.shared.u64 t, %1; cvt.u32.u64 %0, t; }" : "=r"(a) : "l"(p));
    return a;
}

#define CP_ASYNC16(smem, gmem) \
    asm volatile("cp.async.cg.shared.global [%0], [%1], 16;" \
                 :: "r"(smem), "l"(gmem) : "memory")
#define CP_COMMIT() asm volatile("cp.async.commit_group;" ::: "memory")
#define CP_WAIT()   asm volatile("cp.async.wait_group %0;" :: "n"(STAGES - 2) : "memory")

#define LDMATRIX_X4(r0, r1, r2, r3, addr) \
    asm volatile("ldmatrix.sync.aligned.m8n8.x4.shared.b16 {%0,%1,%2,%3}, [%4];" \
                 : "=r"(r0), "=r"(r1), "=r"(r2), "=r"(r3) : "r"(addr))

__device__ __forceinline__ void mma16816(float* c, const uint32_t* a, const uint32_t* b) {
    asm volatile(
        "mma.sync.aligned.m16n8k16.row.col.f32.f16.f16.f32 "
        "{%0,%1,%2,%3}, {%4,%5,%6,%7}, {%8,%9}, {%0,%1,%2,%3};"
        : "+f"(c[0]), "+f"(c[1]), "+f"(c[2]), "+f"(c[3])
        : "r"(a[0]), "r"(a[1]), "r"(a[2]), "r"(a[3]), "r"(b[0]), "r"(b[1]));
}

// ============================================================================
// Fused pre-pass: x fp32->fp16, W int4->fp16, bias dequant.
// ============================================================================
__global__ void prepass_kernel(const float* __restrict__ x,
                               const int* __restrict__ pw,
                               const int* __restrict__ pb,
                               const float* __restrict__ scale_b) {
    int i = blockIdx.x * blockDim.x + threadIdx.x;
    float4 v = reinterpret_cast<const float4*>(x)[i];
    __half2* o = reinterpret_cast<__half2*>(g_xh) + (size_t)i * 2;
    o[0] = __floats2half2_rn(v.x, v.y);
    o[1] = __floats2half2_rn(v.z, v.w);
    int b = pw[i];
    int hi = ((b >> 4) & 15) - 8;
    int lo = (b & 15) - 8;
    reinterpret_cast<__half2*>(g_wh)[i] =
        __halves2half2(__int2half_rn(hi), __int2half_rn(lo));
    if (i < N_TOTAL / 2) {
        float sb = *scale_b;
        int bb = pb[i];
        g_bias[2 * i]     = sb * (float)(((bb >> 4) & 15) - 8);
        g_bias[2 * i + 1] = sb * (float)((bb & 15) - 8);
    }
}

// ============================================================================
// GEMM: 256 threads, CTA tile 128x128, warp tile 64x32, 2 CTAs/SM, 3 stages.
// Round-9 change: compute-first loop — after the barrier warps go STRAIGHT to
// LDSM/MMA; the 8 cp.asyncs for stage kt+2 are interleaved 2-per-ks AFTER each
// MMA block, so crossbar writes ride in the MMA shadow instead of colliding
// with the head LDSM burst (round-8 profile: bursty L1 63% / tensor 76.5%).
// Prefetch slack is ~2 phases (~5000 cyc) vs ~250 cyc L2 latency -> delaying
// issue is free.
// ============================================================================
__global__ void __launch_bounds__(256, 2) gemm_kernel(
    float* __restrict__ out, const float* __restrict__ scale_w_p)
{
    extern __shared__ __align__(1024) char smem[];
    const uint32_t sb = smem_u32(smem);

    const int tid = threadIdx.x;
    const int wid = tid >> 5;
    const int lid = tid & 31;
    const int warp_m = wid & 1;   // 0..1
    const int warp_n = wid >> 1;  // 0..3

    const int m0 = blockIdx.y * TILE_M;
    const int n0 = blockIdx.x * TILE_N;

    // ---- cp.async per-thread constants ----
    const int ld_row = tid >> 3;          // 0..31 row-subgroup
    const int ld_chk = tid & 7;           // 0..7  16B column chunk
    const __half* gA = g_xh + (size_t)(m0 + ld_row) * K_TOTAL + ld_chk * 8;
    const __half* gB = g_wh + (size_t)(n0 + ld_row) * K_TOTAL + ld_chk * 8;
    const uint32_t sw_off = (uint32_t)((ld_chk ^ (ld_row & 7)) << 4);

    // ---- ldmatrix per-lane constants ----
    const int s7 = lid & 7;               // swizzle xor term (row & 7 invariant)
    const int q  = lid >> 3;              // 0..3
    const int a_row = warp_m * 64 + ((q & 1) << 3) + s7;
    const int kc_a = q >> 1;
    const int b_row = warp_n * 32 + ((q >> 1) << 3) + s7;
    const int kc_b = q & 1;

    float acc[4][4][4];
    #pragma unroll
    for (int mt = 0; mt < 4; mt++)
        #pragma unroll
        for (int nt = 0; nt < 4; nt++)
            #pragma unroll
            for (int e = 0; e < 4; e++) acc[mt][nt][e] = 0.0f;

    // ---- prologue: prefetch stages 0..1 ----
    #pragma unroll
    for (int p = 0; p < STAGES - 1; p++) {
        const uint32_t sA = sb + p * STAGE_BYTES;
        const uint32_t sB = sA + A_STAGE_BYTES;
        const int k0 = p * TILE_K;
        #pragma unroll
        for (int i = 0; i < 4; i++)
            CP_ASYNC16(sA + (i * 32 + ld_row) * 128 + sw_off,
                       gA + (size_t)i * 32 * K_TOTAL + k0);
        #pragma unroll
        for (int i = 0; i < 4; i++)
            CP_ASYNC16(sB + (i * 32 + ld_row) * 128 + sw_off,
                       gB + (size_t)i * 32 * K_TOTAL + k0);
        CP_COMMIT();
    }

    // ---- mainloop (compute-first, copies interleaved into ks loop) ----
    int buf = 0;
    int nbuf = STAGES - 1;
    for (int kt = 0; kt < NITER; kt++) {
        CP_WAIT();         // stage kt arrived (this thread)
        __syncthreads();   // publish; nobody still reads nbuf

        const uint32_t sA = sb + buf * STAGE_BYTES;
        const uint32_t sB = sA + A_STAGE_BYTES;
        const uint32_t aBase = sA + a_row * 128;
        const uint32_t bBase = sB + b_row * 128;

        // prefetch target (clamped in tail: harmless redundant in-bounds loads
        // into a buffer that is never consumed; keeps commit count uniform)
        const uint32_t pA = sb + nbuf * STAGE_BYTES;
        const uint32_t pB = pA + A_STAGE_BYTES;
        const int kpref = (kt + STAGES - 1 < NITER) ? (kt + STAGES - 1) * TILE_K : 0;

        uint32_t b_frag[2][4][2];
        // preload B for ks=0
        {
            const uint32_t boff = (uint32_t)((kc_b ^ s7) << 4);
            #pragma unroll
            for (int j = 0; j < 2; j++)
                LDMATRIX_X4(b_frag[0][2 * j][0], b_frag[0][2 * j][1],
                            b_frag[0][2 * j + 1][0], b_frag[0][2 * j + 1][1],
                            bBase + j * 2048 + boff);
        }

        #pragma unroll
        for (int ks = 0; ks < 4; ks++) {
            const int cur = ks & 1;
            const int nxt = cur ^ 1;
            uint32_t a_frag[4][4];
            const uint32_t aoff = (uint32_t)(((ks * 2 + kc_a) ^ s7) << 4);
            #pragma unroll
            for (int mt = 0; mt < 4; mt++)
                LDMATRIX_X4(a_frag[mt][0], a_frag[mt][1], a_frag[mt][2], a_frag[mt][3],
                            aBase + mt * 2048 + aoff);
            if (ks < 3) {   // prefetch B(ks+1)
                const uint32_t boff = (uint32_t)((((ks + 1) * 2 + kc_b) ^ s7) << 4);
                #pragma unroll
                for (int j = 0; j < 2; j++)
                    LDMATRIX_X4(b_frag[nxt][2 * j][0], b_frag[nxt][2 * j][1],
                                b_frag[nxt][2 * j + 1][0], b_frag[nxt][2 * j + 1][1],
                                bBase + j * 2048 + boff);
            }
            #pragma unroll
            for (int mt = 0; mt < 4; mt++)
                #pragma unroll
                for (int nt = 0; nt < 4; nt++)
                    mma16816(acc[mt][nt], a_frag[mt], b_frag[cur][nt]);

            // 2 of the 8 stage-(kt+2) copies, in the shadow of this MMA block
            #pragma unroll
            for (int t = 0; t < 2; t++) {
                const int i = ks * 2 + t;       // 0..7 compile-time
                if (i < 4)
                    CP_ASYNC16(pA + (i * 32 + ld_row) * 128 + sw_off,
                               gA + (size_t)i * 32 * K_TOTAL + kpref);
                else
                    CP_ASYNC16(pB + ((i - 4) * 32 + ld_row) * 128 + sw_off,
                               gB + (size_t)(i - 4) * 32 * K_TOTAL + kpref);
            }
        }
        CP_COMMIT();       // one group per iteration

        buf = (buf + 1 == STAGES) ? 0 : buf + 1;
        nbuf = (nbuf + 1 == STAGES) ? 0 : nbuf + 1;
    }

    // ---- epilogue ----
    const float sw = __ldg(scale_w_p);
    const int mrow = m0 + warp_m * 64 + (lid >> 2);
    const int ncol = n0 + warp_n * 32 + (lid & 3) * 2;

    #pragma unroll
    for (int mt = 0; mt < 4; mt++) {
        #pragma unroll
        for (int nt = 0; nt < 4; nt++) {
            const int m1 = mrow + mt * 16;
            const int n1 = ncol + nt * 8;
            const float b0 = g_bias[n1];
            const float b1 = g_bias[n1 + 1];
            float2 v0 = make_float2(fmaf(sw, acc[mt][nt][0], b0),
                                    fmaf(sw, acc[mt][nt][1], b1));
            float2 v1 = make_float2(fmaf(sw, acc[mt][nt][2], b0),
                                    fmaf(sw, acc[mt][nt][3], b1));
            __stcs(reinterpret_cast<float2*>(out + (size_t)m1 * N_TOTAL + n1), v0);
            __stcs(reinterpret_cast<float2*>(out + (size_t)(m1 + 8) * N_TOTAL + n1), v1);
        }
    }
}

// ============================================================================
// Host
// ============================================================================
extern "C" void kernel_launch(void* const* d_in, const int* in_sizes, int n_in,
                              void* d_out, int out_size) {
    const float* x   = (const float*)d_in[0];
    const int* pw    = (const int*)d_in[1];
    const int* pb    = (const int*)d_in[2];
    const float* sw  = (const float*)d_in[3];
    const float* sbp = (const float*)d_in[4];
    float* out = (float*)d_out;

    prepass_kernel<<<(M_TOTAL * K_TOTAL / 4) / 256, 256>>>(x, pw, pb, sbp);

    cudaFuncSetAttribute(gemm_kernel, cudaFuncAttributeMaxDynamicSharedMemorySize, SMEM_TOTAL);
    dim3 grid(N_TOTAL / TILE_N, M_TOTAL / TILE_M);   // (32, 64)
    gemm_kernel<<<grid, 256, SMEM_TOTAL>>>(out, sw);
}